// round 10
// baseline (speedup 1.0000x reference)
#include <cuda_runtime.h>
#include <cuda_fp16.h>
#include <math.h>

// ---------------- problem constants ----------------
constexpr int NB = 256;    // batch
constexpr int NA = 285;    // angles
constexpr int ND = 183;    // detectors
constexpr int NI = 128;    // image N
constexpr int QQ = 184;    // quads per row (stride)

constexpr double RHO_D    = 1.4142135623730951 * 20.0;
constexpr double DC_D     = 2.0 * RHO_D / 183.0;
constexpr double INVDC_D  = 1.0 / DC_D;
constexpr double H0_D     = 1.0 / (4.0 * DC_D * DC_D);
constexpr double SCALEQ_D = 12.0 * DC_D;
constexpr double PI_D     = 3.141592653589793;

// filtered sinogram, fp16 4-image-interleaved (g0, delta) quads:
// Q[group][a][k] = halfs (g_b0[k],g_b1[k],g_b2[k],g_b3[k],
//                         (g[k+1]-g[k])_b0, ..., _b3)          (16B)
__device__ uint4 g_q[(size_t)(NB / 4) * NA * QQ];

// ================= Stage 1: ramp filter (banded conv) =================
// Block: 4 images (group) x 4 angles = 16 rows; 192 threads.
// Thread map: r = t&15 (row), l = t>>4 (output group of 16).
// -> warp = 16 rows x 2 l: G-window loads broadcast (2 addrs/warp),
//    x-row loads conflict-free with stride 204 (816B = 48 mod 128).
constexpr int XSTR = 204;

__global__ __launch_bounds__(192) void filter_kernel(const float* __restrict__ x,
                                                     uint4* __restrict__ Q) {
    __shared__ __align__(16) float xs[16 * XSTR];    // 16 rows, zero-padded
    __shared__ __align__(16) float Gs[224];          // Godd shifted +8, guarded
    __shared__ __align__(16) __half st[4 * 184 * 4]; // [va][n][im]

    const int t  = threadIdx.x;
    const int a0 = blockIdx.x * 4;                  // angle quad
    const int g  = blockIdx.y;                      // image group
    const int b0 = 4 * g;

    // Gs[j] = g(2*(j-8)-181) for j-8 in [0,181], else 0
    for (int jj = t; jj < 224; jj += 192) {
        int i = jj - 8;
        float v = 0.0f;
        if (i >= 0 && i <= 181) {
            int o = 2 * i - 181;                    // odd
            double d = PI_D * (double)o * DC_D;
            v = (float)(-1.0 / (d * d));
        }
        Gs[jj] = v;
    }

    // load 16 rows (row = va*4 + im), zero-padded to XSTR
    for (int u = t; u < 16 * XSTR; u += 192) {
        int row = u / XSTR, col = u - row * XSTR;
        int va = row >> 2, im = row & 3;
        int aa = a0 + va;
        float v = 0.0f;
        if (col < ND && aa < NA)
            v = x[((size_t)(b0 + im) * NA + aa) * ND + col];
        xs[u] = v;
    }
    __syncthreads();

    const int r  = t & 15;           // row 0..15
    const int l  = t >> 4;           // 0..11
    const int va = r >> 2, im = r & 3;
    const int n0 = 16 * l;
    const int E0 = 8 * l + 90;
    const float* xr = xs + r * XSTR;

    float acc[16];
    #pragma unroll
    for (int e = 0; e < 16; e++) acc[e] = 0.0f;

    // 23 unroll-4 blocks cover s = 0..91 (includes the even m=182 tap;
    // odd m=183 multiplies padded x[183]=0; Gs guard zeros absorb underrun)
    for (int s0 = 0; s0 < 92; s0 += 4) {
        float4 xq0 = *(const float4*)(xr + 2 * s0);      // x[2s0 .. 2s0+3]
        float4 xq1 = *(const float4*)(xr + 2 * s0 + 4);  // x[2s0+4 .. +7]
        const float4* Gv = (const float4*)(Gs + (E0 - s0 + 2)); // 4-aligned
        float4 g0v = Gv[0], g1v = Gv[1], g2v = Gv[2], g3v = Gv[3];
        float gg[16] = {g0v.x,g0v.y,g0v.z,g0v.w, g1v.x,g1v.y,g1v.z,g1v.w,
                        g2v.x,g2v.y,g2v.z,g2v.w, g3v.x,g3v.y,g3v.z,g3v.w};
        float xf[8] = {xq0.x,xq0.y,xq0.z,xq0.w, xq1.x,xq1.y,xq1.z,xq1.w};
        #pragma unroll
        for (int k = 0; k < 4; k++) {
            #pragma unroll
            for (int e = 0; e < 8; e++) {
                acc[2*e]   = fmaf(xf[2*k+1], gg[e + 6 - k], acc[2*e]);   // even n
                acc[2*e+1] = fmaf(xf[2*k],   gg[e + 7 - k], acc[2*e+1]); // odd n
            }
        }
    }
    { // center tap
        const float h0 = (float)H0_D;
        float4 c0 = *(const float4*)(xr + n0);
        float4 c1 = *(const float4*)(xr + n0 + 4);
        float4 c2 = *(const float4*)(xr + n0 + 8);
        float4 c3 = *(const float4*)(xr + n0 + 12);
        float cf[16] = {c0.x,c0.y,c0.z,c0.w, c1.x,c1.y,c1.z,c1.w,
                        c2.x,c2.y,c2.z,c2.w, c3.x,c3.y,c3.z,c3.w};
        #pragma unroll
        for (int e = 0; e < 16; e++) acc[e] = fmaf(h0, cf[e], acc[e]);
    }

    // stage as fp16: st[(va*184 + n)*4 + im]
    const float sc = (float)SCALEQ_D;
    #pragma unroll
    for (int e = 0; e < 16; e++) {
        int n = n0 + e;
        if (n < 184) st[(va * 184 + n) * 4 + im] = __float2half_rn(acc[e] * sc);
    }
    __syncthreads();

    // pack (g0, delta) quads
    for (int u = t; u < 4 * ND; u += 192) {
        int qa = u / ND, k = u - qa * ND;
        int aa = a0 + qa;
        if (aa < NA) {
            const uint2* sp = (const uint2*)(st + qa * 184 * 4);
            uint2 lo = sp[k];
            uint2 hi = sp[k + 1];
            __half2 dd0 = __hsub2(*(const __half2*)&hi.x, *(const __half2*)&lo.x);
            __half2 dd1 = __hsub2(*(const __half2*)&hi.y, *(const __half2*)&lo.y);
            Q[((size_t)g * NA + aa) * QQ + k] =
                make_uint4(lo.x, lo.y, *(const unsigned*)&dd0, *(const unsigned*)&dd1);
        }
    }
}

// ================= Stage 2: backprojection =================
// 4-buffer ring (dynamic smem), 3-deep pipeline of 2-angle stages,
// ONE barrier per stage: the slot written by prefetch(stg+3) is (stg-1)&3,
// which every warp finished reading before this stage's top barrier.
constexpr int APS    = 2;
constexpr int STAGES = (NA + APS - 1) / APS;   // 143
constexpr int CHUNK  = APS * 2 * QQ;           // 736
constexpr unsigned CHUNKB = CHUNK * 16;
constexpr unsigned DYN_SMEM = 4 * CHUNKB;      // 47104 bytes

__device__ __forceinline__ void cp_async16(unsigned dst, const void* src) {
    asm volatile("cp.async.cg.shared.global [%0], [%1], 16;" :: "r"(dst), "l"(src));
}

__global__ __launch_bounds__(256) void backproj_kernel(const uint4* __restrict__ Q,
                                                       float* __restrict__ out) {
    extern __shared__ __align__(16) unsigned char dynsmem[];
    uint4* qb = (uint4*)dynsmem;                 // [4][CHUNK]
    __shared__ float2 csn[NA];

    const int t   = threadIdx.x;
    const int seg = blockIdx.x;        // 0..31 -> image rows [seg*4, seg*4+4)
    const int bg  = blockIdx.y;        // 0..31 -> images [bg*8, bg*8+8)

    for (int idx = t; idx < NA; idx += 256) {
        double th = ((double)idx + 0.5) * (PI_D / (double)NA);
        double s, c;
        sincos(th, &s, &c);
        csn[idx] = make_float2((float)(c * INVDC_D), (float)(s * INVDC_D));
    }

    const int j  = t & 127;
    const int i0 = seg * 4 + (t >> 7) * 2;
    const float Yj = -20.0f + ((float)j  + 0.5f) * 0.3125f;
    const float Xi = -20.0f + ((float)i0 + 0.5f) * 0.3125f;

    const uint4* Qb = Q + (size_t)(bg * 2) * NA * QQ;

    // hoisted 3-slot chunk decomposition over [0, 736)
    const int pp0 = t / 184,               c0i = t - pp0 * 184;
    const int u1  = t + 256;
    const int ai1 = (u1 >= 368) ? 1 : 0;
    const int v1  = u1 - ai1 * 368;
    const int pp1 = v1 / 184,              c1i = v1 - pp1 * 184;
    const int u2  = t + 512;
    const bool has2 = (u2 < CHUNK);
    const int v2  = u2 - 368;
    const int pp2 = has2 ? (v2 / 184) : 0, c2i = has2 ? (v2 - (v2 / 184) * 184) : 0;

    const uint4* src0 = Qb + ((size_t)pp0 * NA + 0  ) * QQ + c0i;
    const uint4* src1 = Qb + ((size_t)pp1 * NA + ai1) * QQ + c1i;
    const uint4* src2 = Qb + ((size_t)pp2 * NA + 1  ) * QQ + c2i;

    const unsigned sb = (unsigned)__cvta_generic_to_shared(qb);
    const unsigned d0 = sb + (unsigned)(((0  * 2 + pp0) * QQ + c0i) * 16);
    const unsigned d1 = sb + (unsigned)(((ai1 * 2 + pp1) * QQ + c1i) * 16);
    const unsigned d2 = sb + (unsigned)(((1  * 2 + pp2) * QQ + c2i) * 16);

    // prologue: prefetch stages 0..2 into buffers 0..2
    #pragma unroll
    for (int s = 0; s < 3; s++) {
        unsigned off = s * CHUNKB;
        cp_async16(d0 + off, src0);
        cp_async16(d1 + off, src1);
        if (has2) cp_async16(d2 + off, src2);
        asm volatile("cp.async.commit_group;");
        src0 += APS * QQ; src1 += APS * QQ; src2 += APS * QQ;
    }

    float acc[8][2];
    #pragma unroll
    for (int v = 0; v < 8; v++) { acc[v][0] = 0.0f; acc[v][1] = 0.0f; }

    for (int stg = 0; stg < STAGES; stg++) {
        asm volatile("cp.async.wait_group 2;");
        __syncthreads();   // buffer stg&3 ready; slot (stg+3)&3 fully consumed

        // prefetch stage stg+3 into ring slot (stg+3)&3; always commit
        const int stp = stg + 3;
        if (stp < STAGES) {
            const unsigned off = (unsigned)(stp & 3) * CHUNKB;
            const bool full = (2 * stp + 1 < NA);
            cp_async16(d0 + off, src0);
            if (full || ai1 == 0) cp_async16(d1 + off, src1);
            if (has2 && full)     cp_async16(d2 + off, src2);
            src0 += APS * QQ; src1 += APS * QQ; src2 += APS * QQ;
        }
        asm volatile("cp.async.commit_group;");

        const int a0 = 2 * stg;
        const uint4* qs = qb + (size_t)(stg & 3) * CHUNK;

        #pragma unroll
        for (int ai = 0; ai < APS; ai++) {
            if (ai == 1 && a0 + 1 >= NA) break;   // only last stage
            const float2 cs  = csn[a0 + ai];
            const float  kf0 = fmaf(cs.x, Xi, fmaf(cs.y, Yj, 91.0f));
            const float  dk  = cs.x * 0.3125f;
            const uint4* qc  = qs + ai * (2 * QQ);

            #pragma unroll
            for (int ii = 0; ii < 2; ii++) {
                float kf = fmaf((float)ii, dk, kf0);
                int   k0 = (int)kf;                 // kf in [0.2, 181.8]
                float w  = kf - (float)k0;
                __half2 w2 = __floats2half2_rn(w, w);
                #pragma unroll
                for (int gq = 0; gq < 2; gq++) {
                    uint4 qd = qc[gq * QQ + k0];                 // LDS.128
                    __half2 g0lo = *(const __half2*)&qd.x;       // (b0,b1)
                    __half2 g0hi = *(const __half2*)&qd.y;       // (b2,b3)
                    __half2 dlo  = *(const __half2*)&qd.z;
                    __half2 dhi  = *(const __half2*)&qd.w;
                    __half2 tlo = __hfma2(w2, dlo, g0lo);
                    __half2 thi = __hfma2(w2, dhi, g0hi);
                    acc[gq * 4 + 0][ii] += __low2float(tlo);
                    acc[gq * 4 + 1][ii] += __high2float(tlo);
                    acc[gq * 4 + 2][ii] += __low2float(thi);
                    acc[gq * 4 + 3][ii] += __high2float(thi);
                }
            }
        }
    }

    const float sc = (float)(PI_D / (double)NA);
    #pragma unroll
    for (int gq = 0; gq < 2; gq++) {
        #pragma unroll
        for (int rr = 0; rr < 4; rr++) {
            int img = bg * 8 + gq * 4 + rr;
            #pragma unroll
            for (int ii = 0; ii < 2; ii++) {
                out[(size_t)img * (NI * NI) + (size_t)(i0 + ii) * NI + j] =
                    acc[gq * 4 + rr][ii] * sc;
            }
        }
    }
}

// ================= launch =================
extern "C" void kernel_launch(void* const* d_in, const int* in_sizes, int n_in,
                              void* d_out, int out_size) {
    (void)in_sizes; (void)n_in; (void)out_size;
    const float* x = (const float*)d_in[0];
    float* out = (float*)d_out;

    uint4* qptr = nullptr;
    cudaGetSymbolAddress((void**)&qptr, g_q);

    cudaFuncSetAttribute(backproj_kernel,
                         cudaFuncAttributeMaxDynamicSharedMemorySize, DYN_SMEM);

    filter_kernel<<<dim3((NA + 3) / 4, NB / 4), 192>>>(x, qptr);
    backproj_kernel<<<dim3(32, 32), 256, DYN_SMEM>>>(qptr, out);
}

// round 11
// speedup vs baseline: 1.0865x; 1.0865x over previous
#include <cuda_runtime.h>
#include <cuda_fp16.h>
#include <math.h>

// ---------------- problem constants ----------------
constexpr int NB = 256;    // batch
constexpr int NA = 285;    // angles
constexpr int ND = 183;    // detectors
constexpr int NI = 128;    // image N
constexpr int QQ = 184;    // quads per row (stride)

constexpr double RHO_D    = 1.4142135623730951 * 20.0;
constexpr double DC_D     = 2.0 * RHO_D / 183.0;
constexpr double INVDC_D  = 1.0 / DC_D;
constexpr double H0_D     = 1.0 / (4.0 * DC_D * DC_D);
constexpr double SCALEQ_D = 12.0 * DC_D;
constexpr double PI_D     = 3.141592653589793;

// filtered sinogram, fp16 4-image-interleaved (g0, delta) quads:
// Q[group][a][k] = halfs (g_b0[k],g_b1[k],g_b2[k],g_b3[k],
//                         (g[k+1]-g[k])_b0, ..., _b3)          (16B)
__device__ uint4 g_q[(size_t)(NB / 4) * NA * QQ];

// ================= Stage 1: ramp filter (banded conv) =================
// Block: 4 images (group) x 4 angles = 16 rows; 192 threads.
// Thread map: r = t&15 (row), l = t>>4 (output group of 16).
// -> warp = 16 rows x 2 l: G-window loads broadcast (2 addrs/warp),
//    x-row loads conflict-free with stride 204 (816B = 48 mod 128).
constexpr int XSTR = 204;

__global__ __launch_bounds__(192) void filter_kernel(const float* __restrict__ x,
                                                     uint4* __restrict__ Q) {
    __shared__ __align__(16) float xs[16 * XSTR];    // 16 rows, zero-padded
    __shared__ __align__(16) float Gs[224];          // Godd shifted +8, guarded
    __shared__ __align__(16) __half st[4 * 184 * 4]; // [va][n][im]

    const int t  = threadIdx.x;
    const int a0 = blockIdx.x * 4;                  // angle quad
    const int g  = blockIdx.y;                      // image group
    const int b0 = 4 * g;

    // Gs[j] = g(2*(j-8)-181) for j-8 in [0,181], else 0
    for (int jj = t; jj < 224; jj += 192) {
        int i = jj - 8;
        float v = 0.0f;
        if (i >= 0 && i <= 181) {
            int o = 2 * i - 181;                    // odd
            double d = PI_D * (double)o * DC_D;
            v = (float)(-1.0 / (d * d));
        }
        Gs[jj] = v;
    }

    // load 16 rows (row = va*4 + im), zero-padded to XSTR
    for (int u = t; u < 16 * XSTR; u += 192) {
        int row = u / XSTR, col = u - row * XSTR;
        int va = row >> 2, im = row & 3;
        int aa = a0 + va;
        float v = 0.0f;
        if (col < ND && aa < NA)
            v = x[((size_t)(b0 + im) * NA + aa) * ND + col];
        xs[u] = v;
    }
    __syncthreads();

    const int r  = t & 15;           // row 0..15
    const int l  = t >> 4;           // 0..11
    const int va = r >> 2, im = r & 3;
    const int n0 = 16 * l;
    const int E0 = 8 * l + 90;
    const float* xr = xs + r * XSTR;

    float acc[16];
    #pragma unroll
    for (int e = 0; e < 16; e++) acc[e] = 0.0f;

    // 23 unroll-4 blocks cover s = 0..91 (includes the even m=182 tap;
    // odd m=183 multiplies padded x[183]=0; Gs guard zeros absorb underrun)
    for (int s0 = 0; s0 < 92; s0 += 4) {
        float4 xq0 = *(const float4*)(xr + 2 * s0);      // x[2s0 .. 2s0+3]
        float4 xq1 = *(const float4*)(xr + 2 * s0 + 4);  // x[2s0+4 .. +7]
        const float4* Gv = (const float4*)(Gs + (E0 - s0 + 2)); // 4-aligned
        float4 g0v = Gv[0], g1v = Gv[1], g2v = Gv[2], g3v = Gv[3];
        float gg[16] = {g0v.x,g0v.y,g0v.z,g0v.w, g1v.x,g1v.y,g1v.z,g1v.w,
                        g2v.x,g2v.y,g2v.z,g2v.w, g3v.x,g3v.y,g3v.z,g3v.w};
        float xf[8] = {xq0.x,xq0.y,xq0.z,xq0.w, xq1.x,xq1.y,xq1.z,xq1.w};
        #pragma unroll
        for (int k = 0; k < 4; k++) {
            #pragma unroll
            for (int e = 0; e < 8; e++) {
                acc[2*e]   = fmaf(xf[2*k+1], gg[e + 6 - k], acc[2*e]);   // even n
                acc[2*e+1] = fmaf(xf[2*k],   gg[e + 7 - k], acc[2*e+1]); // odd n
            }
        }
    }
    { // center tap
        const float h0 = (float)H0_D;
        float4 c0 = *(const float4*)(xr + n0);
        float4 c1 = *(const float4*)(xr + n0 + 4);
        float4 c2 = *(const float4*)(xr + n0 + 8);
        float4 c3 = *(const float4*)(xr + n0 + 12);
        float cf[16] = {c0.x,c0.y,c0.z,c0.w, c1.x,c1.y,c1.z,c1.w,
                        c2.x,c2.y,c2.z,c2.w, c3.x,c3.y,c3.z,c3.w};
        #pragma unroll
        for (int e = 0; e < 16; e++) acc[e] = fmaf(h0, cf[e], acc[e]);
    }

    // stage as fp16: st[(va*184 + n)*4 + im]
    const float sc = (float)SCALEQ_D;
    #pragma unroll
    for (int e = 0; e < 16; e++) {
        int n = n0 + e;
        if (n < 184) st[(va * 184 + n) * 4 + im] = __float2half_rn(acc[e] * sc);
    }
    __syncthreads();

    // pack (g0, delta) quads
    for (int u = t; u < 4 * ND; u += 192) {
        int qa = u / ND, k = u - qa * ND;
        int aa = a0 + qa;
        if (aa < NA) {
            const uint2* sp = (const uint2*)(st + qa * 184 * 4);
            uint2 lo = sp[k];
            uint2 hi = sp[k + 1];
            __half2 dd0 = __hsub2(*(const __half2*)&hi.x, *(const __half2*)&lo.x);
            __half2 dd1 = __hsub2(*(const __half2*)&hi.y, *(const __half2*)&lo.y);
            Q[((size_t)g * NA + aa) * QQ + k] =
                make_uint4(lo.x, lo.y, *(const unsigned*)&dd0, *(const unsigned*)&dd1);
        }
    }
}

// ================= Stage 2: backprojection =================
// R7 memory config (static 3-buffer, 5 blocks/SM) + stage-paired fp16
// accumulation: both angles of a stage are lerped in fp16, summed with one
// HADD2, and converted/accumulated to f32 once -> ~21% fewer inner slots,
// no persistent half2 registers.
constexpr int APS    = 2;
constexpr int STAGES = (NA + APS - 1) / APS;   // 143
constexpr int CHUNK  = APS * 2 * QQ;           // 736
constexpr unsigned CHUNKB = CHUNK * 16;

__device__ __forceinline__ void cp_async16(unsigned dst, const void* src) {
    asm volatile("cp.async.cg.shared.global [%0], [%1], 16;" :: "r"(dst), "l"(src));
}

__global__ __launch_bounds__(256, 5) void backproj_kernel(const uint4* __restrict__ Q,
                                                          float* __restrict__ out) {
    __shared__ uint4  qb[3][CHUNK];
    __shared__ float2 csn[NA];

    const int t   = threadIdx.x;
    const int seg = blockIdx.x;        // 0..31 -> image rows [seg*4, seg*4+4)
    const int bg  = blockIdx.y;        // 0..31 -> images [bg*8, bg*8+8)

    for (int idx = t; idx < NA; idx += 256) {
        double th = ((double)idx + 0.5) * (PI_D / (double)NA);
        double s, c;
        sincos(th, &s, &c);
        csn[idx] = make_float2((float)(c * INVDC_D), (float)(s * INVDC_D));
    }

    const int j  = t & 127;
    const int i0 = seg * 4 + (t >> 7) * 2;
    const float Yj = -20.0f + ((float)j  + 0.5f) * 0.3125f;
    const float Xi = -20.0f + ((float)i0 + 0.5f) * 0.3125f;

    const uint4* Qb = Q + (size_t)(bg * 2) * NA * QQ;

    // hoisted 3-slot chunk decomposition over [0, 736)
    const int pp0 = t / 184,               c0i = t - pp0 * 184;
    const int u1  = t + 256;
    const int ai1 = (u1 >= 368) ? 1 : 0;
    const int v1  = u1 - ai1 * 368;
    const int pp1 = v1 / 184,              c1i = v1 - pp1 * 184;
    const int u2  = t + 512;
    const bool has2 = (u2 < CHUNK);
    const int v2  = u2 - 368;
    const int pp2 = has2 ? (v2 / 184) : 0, c2i = has2 ? (v2 - (v2 / 184) * 184) : 0;

    const uint4* src0 = Qb + ((size_t)pp0 * NA + 0  ) * QQ + c0i;
    const uint4* src1 = Qb + ((size_t)pp1 * NA + ai1) * QQ + c1i;
    const uint4* src2 = Qb + ((size_t)pp2 * NA + 1  ) * QQ + c2i;

    const unsigned sb = (unsigned)__cvta_generic_to_shared(&qb[0][0]);
    const unsigned d0 = sb + (unsigned)(((0  * 2 + pp0) * QQ + c0i) * 16);
    const unsigned d1 = sb + (unsigned)(((ai1 * 2 + pp1) * QQ + c1i) * 16);
    const unsigned d2 = sb + (unsigned)(((1  * 2 + pp2) * QQ + c2i) * 16);

    // prologue: prefetch stages 0..2 into buffers 0..2
    #pragma unroll
    for (int s = 0; s < 3; s++) {
        unsigned off = s * CHUNKB;
        cp_async16(d0 + off, src0);
        cp_async16(d1 + off, src1);
        if (has2) cp_async16(d2 + off, src2);
        asm volatile("cp.async.commit_group;");
        src0 += APS * QQ; src1 += APS * QQ; src2 += APS * QQ;
    }

    float acc[8][2];
    #pragma unroll
    for (int v = 0; v < 8; v++) { acc[v][0] = 0.0f; acc[v][1] = 0.0f; }

    int cur = 0;
    for (int stg = 0; stg < STAGES; stg++) {
        asm volatile("cp.async.wait_group 2;");
        __syncthreads();

        const int a0 = 2 * stg;
        const uint4* qs = qb[cur];

        if (a0 + 1 < NA) {
            // ---- dual-angle stage (142 of 143) ----
            const float2 csA = csn[a0];
            const float2 csB = csn[a0 + 1];
            const float kfA = fmaf(csA.x, Xi, fmaf(csA.y, Yj, 91.0f));
            const float kfB = fmaf(csB.x, Xi, fmaf(csB.y, Yj, 91.0f));
            const float dkA = csA.x * 0.3125f;
            const float dkB = csB.x * 0.3125f;

            #pragma unroll
            for (int ii = 0; ii < 2; ii++) {
                float ka = fmaf((float)ii, dkA, kfA);
                float kb = fmaf((float)ii, dkB, kfB);
                int k0a = (int)ka;                  // in [0.2, 181.8]
                int k0b = (int)kb;
                float wa = ka - (float)k0a;
                float wb = kb - (float)k0b;
                __half2 w2a = __floats2half2_rn(wa, wa);
                __half2 w2b = __floats2half2_rn(wb, wb);
                #pragma unroll
                for (int gq = 0; gq < 2; gq++) {
                    uint4 qA = qs[gq * QQ + k0a];            // angle a0
                    uint4 qB = qs[2 * QQ + gq * QQ + k0b];   // angle a0+1
                    __half2 lo = __hadd2(
                        __hfma2(w2a, *(const __half2*)&qA.z, *(const __half2*)&qA.x),
                        __hfma2(w2b, *(const __half2*)&qB.z, *(const __half2*)&qB.x));
                    __half2 hi = __hadd2(
                        __hfma2(w2a, *(const __half2*)&qA.w, *(const __half2*)&qA.y),
                        __hfma2(w2b, *(const __half2*)&qB.w, *(const __half2*)&qB.y));
                    acc[gq * 4 + 0][ii] += __low2float(lo);
                    acc[gq * 4 + 1][ii] += __high2float(lo);
                    acc[gq * 4 + 2][ii] += __low2float(hi);
                    acc[gq * 4 + 3][ii] += __high2float(hi);
                }
            }
        } else {
            // ---- single-angle tail (stage 142: angle 284) ----
            const float2 csA = csn[a0];
            const float kfA = fmaf(csA.x, Xi, fmaf(csA.y, Yj, 91.0f));
            const float dkA = csA.x * 0.3125f;
            #pragma unroll
            for (int ii = 0; ii < 2; ii++) {
                float ka = fmaf((float)ii, dkA, kfA);
                int k0a = (int)ka;
                float wa = ka - (float)k0a;
                __half2 w2a = __floats2half2_rn(wa, wa);
                #pragma unroll
                for (int gq = 0; gq < 2; gq++) {
                    uint4 qA = qs[gq * QQ + k0a];
                    __half2 lo = __hfma2(w2a, *(const __half2*)&qA.z,
                                         *(const __half2*)&qA.x);
                    __half2 hi = __hfma2(w2a, *(const __half2*)&qA.w,
                                         *(const __half2*)&qA.y);
                    acc[gq * 4 + 0][ii] += __low2float(lo);
                    acc[gq * 4 + 1][ii] += __high2float(lo);
                    acc[gq * 4 + 2][ii] += __low2float(hi);
                    acc[gq * 4 + 3][ii] += __high2float(hi);
                }
            }
        }

        __syncthreads();   // all warps done reading qb[cur]

        // prefetch stage stg+3 into the freed buffer; always commit
        const int stp = stg + 3;
        if (stp < STAGES) {
            const unsigned off = cur * CHUNKB;
            const bool full = (2 * stp + 1 < NA);
            cp_async16(d0 + off, src0);
            if (full || ai1 == 0) cp_async16(d1 + off, src1);
            if (has2 && full)     cp_async16(d2 + off, src2);
            src0 += APS * QQ; src1 += APS * QQ; src2 += APS * QQ;
        }
        asm volatile("cp.async.commit_group;");

        cur = (cur == 2) ? 0 : cur + 1;
    }

    const float sc = (float)(PI_D / (double)NA);
    #pragma unroll
    for (int gq = 0; gq < 2; gq++) {
        #pragma unroll
        for (int rr = 0; rr < 4; rr++) {
            int img = bg * 8 + gq * 4 + rr;
            #pragma unroll
            for (int ii = 0; ii < 2; ii++) {
                out[(size_t)img * (NI * NI) + (size_t)(i0 + ii) * NI + j] =
                    acc[gq * 4 + rr][ii] * sc;
            }
        }
    }
}

// ================= launch =================
extern "C" void kernel_launch(void* const* d_in, const int* in_sizes, int n_in,
                              void* d_out, int out_size) {
    (void)in_sizes; (void)n_in; (void)out_size;
    const float* x = (const float*)d_in[0];
    float* out = (float*)d_out;

    uint4* qptr = nullptr;
    cudaGetSymbolAddress((void**)&qptr, g_q);

    filter_kernel<<<dim3((NA + 3) / 4, NB / 4), 192>>>(x, qptr);
    backproj_kernel<<<dim3(32, 32), 256>>>(qptr, out);
}